// round 10
// baseline (speedup 1.0000x reference)
#include <cuda_runtime.h>
#include <cuda_bf16.h>
#include <cstdint>

// Focal loss (log10 variant) mean over 28.3M elems. HBM-bound: 226.5 MB read.
// R7 skeleton unchanged (1152x256 single exact wave, depth-2 prefetch, fused
// deterministic last-block reduce). ONLY change: __ldcs (evict-first
// streaming) on the two hot-loop load streams — data is touched exactly once,
// so keep it out of L2's retention path. Isolated cache-policy experiment.
// (Third submission — R8/R9 both died to container-acquisition infra
// failures before compile/execution; source never ran.)

#define NBLOCKS   1152
#define NTHREADS  256

__device__ float        g_partials[NBLOCKS];
__device__ unsigned int g_count = 0;

__device__ __forceinline__ float focal_elem(float p, int y) {
    bool  pos = (y != 0);
    float pt  = pos ? p : 1.0f - p;
    float om  = 1.0f - pt;
    // -log10(pt) = -log2(pt) * log10(2)
    float lt  = -__log2f(pt) * 0.3010299956639812f;
    float w   = pos ? 0.9f : 0.1f;
    return w * om * om * lt;
}

__device__ __forceinline__ float focal_vec(float4 p, int4 t) {
    float a = focal_elem(p.x, t.x);
    a += focal_elem(p.y, t.y);
    a += focal_elem(p.z, t.z);
    a += focal_elem(p.w, t.w);
    return a;
}

__global__ void __launch_bounds__(NTHREADS, 8)
focal_fused_kernel(const float4* __restrict__ p4,
                   const int4*   __restrict__ t4,
                   int nvec, int ntail,
                   const float* __restrict__ p_tail,
                   const int*   __restrict__ t_tail,
                   float* __restrict__ out, float inv_n) {
    const int stride = gridDim.x * blockDim.x;
    int i = blockIdx.x * blockDim.x + threadIdx.x;

    float acc = 0.0f;

    if (i < nvec) {
        // prime the pipeline (streaming loads: touched exactly once)
        float4 pc = __ldcs(p4 + i);
        int4   tc = __ldcs(t4 + i);
        int    in = i + stride;

        while (in < nvec) {
            // issue next loads before consuming current values
            float4 pn = __ldcs(p4 + in);
            int4   tn = __ldcs(t4 + in);
            acc += focal_vec(pc, tc);
            pc = pn;
            tc = tn;
            in += stride;
        }
        acc += focal_vec(pc, tc);
    }

    if (blockIdx.x == 0) {
        for (int k = threadIdx.x; k < ntail; k += blockDim.x)
            acc += focal_elem(p_tail[k], t_tail[k]);
    }

    // intra-block reduce
    #pragma unroll
    for (int off = 16; off > 0; off >>= 1)
        acc += __shfl_xor_sync(0xFFFFFFFFu, acc, off);

    __shared__ float smem[NTHREADS / 32];
    int lane = threadIdx.x & 31;
    int wid  = threadIdx.x >> 5;
    if (lane == 0) smem[wid] = acc;
    __syncthreads();

    __shared__ bool s_last;
    if (threadIdx.x == 0) {
        float v = 0.0f;
        #pragma unroll
        for (int w = 0; w < NTHREADS / 32; w++) v += smem[w];
        g_partials[blockIdx.x] = v;
        __threadfence();
        unsigned int prev = atomicAdd(&g_count, 1u);
        s_last = (prev == (unsigned int)(gridDim.x - 1));
    }
    __syncthreads();

    if (s_last) {
        // deterministic final reduction: fixed per-thread order, then tree
        float v = 0.0f;
        #pragma unroll
        for (int k = threadIdx.x; k < NBLOCKS; k += NTHREADS)
            v += g_partials[k];

        #pragma unroll
        for (int off = 16; off > 0; off >>= 1)
            v += __shfl_xor_sync(0xFFFFFFFFu, v, off);

        if (lane == 0) smem[wid] = v;
        __syncthreads();

        if (wid == 0) {
            float s = (lane < NTHREADS / 32) ? smem[lane] : 0.0f;
            #pragma unroll
            for (int off = 4; off > 0; off >>= 1)
                s += __shfl_xor_sync(0xFFFFFFFFu, s, off);
            if (lane == 0) {
                out[0] = s * inv_n;
                g_count = 0;           // reset for next graph replay
                __threadfence();
            }
        }
    }
}

extern "C" void kernel_launch(void* const* d_in, const int* in_sizes, int n_in,
                              void* d_out, int out_size) {
    const float* p = (const float*)d_in[0];
    const int*   t = (const int*)d_in[1];
    int n = in_sizes[0];

    int nvec  = n >> 2;
    int ntail = n - (nvec << 2);

    focal_fused_kernel<<<NBLOCKS, NTHREADS>>>(
        (const float4*)p, (const int4*)t, nvec, ntail,
        p + (nvec << 2), t + (nvec << 2),
        (float*)d_out, 1.0f / (float)n);
}

// round 11
// speedup vs baseline: 1.0008x; 1.0008x over previous
#include <cuda_runtime.h>
#include <cuda_bf16.h>
#include <cstdint>

// FINAL — Focal loss (log10 variant) mean over 28.3M elems.
// Strictly HBM-bound: 226.5 MB irreducible read, one scalar out.
//
// Converged configuration (best measured, R7 = 38.91 us, 5.92 TB/s):
//  - 1152 blocks x 256 threads = 294912 threads -> exactly 24 vec4/thread,
//    all blocks resident in ONE wave (launch_bounds(256,8) pins regs <= 32).
//  - Uninterrupted grid-stride stream with depth-2 software prefetch
//    (next iteration's LDG.128s issued before consuming current values).
//  - Fused deterministic reduction: per-block partials -> last-arriving
//    block sums them in fixed index order (atomic only counts arrivals,
//    never orders float math) -> bit-identical across graph replays;
//    counters reset for replay safety.
// Falsified levers (all flat vs the 5.9 TB/s plateau): MLP x2, work-stealing
// balance, residency 85->96%, __ldcs streaming policy.

#define NBLOCKS   1152
#define NTHREADS  256

__device__ float        g_partials[NBLOCKS];
__device__ unsigned int g_count = 0;

__device__ __forceinline__ float focal_elem(float p, int y) {
    bool  pos = (y != 0);
    float pt  = pos ? p : 1.0f - p;
    float om  = 1.0f - pt;
    // -log10(pt) = -log2(pt) * log10(2)
    float lt  = -__log2f(pt) * 0.3010299956639812f;
    float w   = pos ? 0.9f : 0.1f;
    return w * om * om * lt;
}

__device__ __forceinline__ float focal_vec(float4 p, int4 t) {
    float a = focal_elem(p.x, t.x);
    a += focal_elem(p.y, t.y);
    a += focal_elem(p.z, t.z);
    a += focal_elem(p.w, t.w);
    return a;
}

__global__ void __launch_bounds__(NTHREADS, 8)
focal_fused_kernel(const float4* __restrict__ p4,
                   const int4*   __restrict__ t4,
                   int nvec, int ntail,
                   const float* __restrict__ p_tail,
                   const int*   __restrict__ t_tail,
                   float* __restrict__ out, float inv_n) {
    const int stride = gridDim.x * blockDim.x;
    int i = blockIdx.x * blockDim.x + threadIdx.x;

    float acc = 0.0f;

    if (i < nvec) {
        // prime the pipeline
        float4 pc = p4[i];
        int4   tc = t4[i];
        int    in = i + stride;

        while (in < nvec) {
            // issue next loads before consuming current values
            float4 pn = p4[in];
            int4   tn = t4[in];
            acc += focal_vec(pc, tc);
            pc = pn;
            tc = tn;
            in += stride;
        }
        acc += focal_vec(pc, tc);
    }

    if (blockIdx.x == 0) {
        for (int k = threadIdx.x; k < ntail; k += blockDim.x)
            acc += focal_elem(p_tail[k], t_tail[k]);
    }

    // intra-block reduce
    #pragma unroll
    for (int off = 16; off > 0; off >>= 1)
        acc += __shfl_xor_sync(0xFFFFFFFFu, acc, off);

    __shared__ float smem[NTHREADS / 32];
    int lane = threadIdx.x & 31;
    int wid  = threadIdx.x >> 5;
    if (lane == 0) smem[wid] = acc;
    __syncthreads();

    __shared__ bool s_last;
    if (threadIdx.x == 0) {
        float v = 0.0f;
        #pragma unroll
        for (int w = 0; w < NTHREADS / 32; w++) v += smem[w];
        g_partials[blockIdx.x] = v;
        __threadfence();
        unsigned int prev = atomicAdd(&g_count, 1u);
        s_last = (prev == (unsigned int)(gridDim.x - 1));
    }
    __syncthreads();

    if (s_last) {
        // deterministic final reduction: fixed per-thread order, then tree
        float v = 0.0f;
        #pragma unroll
        for (int k = threadIdx.x; k < NBLOCKS; k += NTHREADS)
            v += g_partials[k];

        #pragma unroll
        for (int off = 16; off > 0; off >>= 1)
            v += __shfl_xor_sync(0xFFFFFFFFu, v, off);

        if (lane == 0) smem[wid] = v;
        __syncthreads();

        if (wid == 0) {
            float s = (lane < NTHREADS / 32) ? smem[lane] : 0.0f;
            #pragma unroll
            for (int off = 4; off > 0; off >>= 1)
                s += __shfl_xor_sync(0xFFFFFFFFu, s, off);
            if (lane == 0) {
                out[0] = s * inv_n;
                g_count = 0;           // reset for next graph replay
                __threadfence();
            }
        }
    }
}

extern "C" void kernel_launch(void* const* d_in, const int* in_sizes, int n_in,
                              void* d_out, int out_size) {
    const float* p = (const float*)d_in[0];
    const int*   t = (const int*)d_in[1];
    int n = in_sizes[0];

    int nvec  = n >> 2;
    int ntail = n - (nvec << 2);

    focal_fused_kernel<<<NBLOCKS, NTHREADS>>>(
        (const float4*)p, (const int4*)t, nvec, ntail,
        p + (nvec << 2), t + (nvec << 2),
        (float*)d_out, 1.0f / (float)n);
}